// round 12
// baseline (speedup 1.0000x reference)
#include <cuda_runtime.h>
#include <cuda_bf16.h>
#include <cstdint>

// ---------------------------------------------------------------------------
// FullGapModel collapse:
//   out[s] = sum_{i: row_seg[i]==s} (x_i^T Q x_i) / ||x_i||^2
//   Q[a,b] = sum_j weights[col_seg[j]] * SP[j,a] * SP[j,b]   (400x400, sym)
//
// HMMA bf16 (mma.sync m16n8k16) with 3-product split precision:
//   D = Xhi*Qhi + Xlo*Qhi + Xhi*Qlo     (error ~ eps_bf16^2)
// R12: flat (nc,sl) iteration with a 3-stage cp.async ring -> ONE
// __syncthreads per K slice and no pipeline drain at N-chunk boundaries.
// ---------------------------------------------------------------------------

#define D_DIM     400
#define KPADX     416          // K padded: 13 slices of 32
#define NSLICE    13
#define NPADQ     448          // Q rows padded: 7 chunks of 64
#define NCHUNK    7
#define TOTS      (NSLICE * NCHUNK)   // 91
#define BM        128
#define BN        64
#define NROWS_PAD 100096       // 782 * 128

#define AS_ST     40                       // bf16 elems per smem row (32+8 pad)
#define A_EL      (BM * AS_ST)             // 5120
#define B_EL      (BN * AS_ST)             // 2560
#define O_AHI     0
#define O_ALO     A_EL
#define O_BHI     (2 * A_EL)
#define O_BLO     (2 * A_EL + B_EL)
#define STAGE_EL  (2 * A_EL + 2 * B_EL)    // 15360 elems = 30720 B
#define NSTG      3
#define SV_OFF    (NSTG * STAGE_EL * 2)    // bytes: 92160
#define SN_OFF    (SV_OFF + BM * 4)
#define SMEM_TOTAL (SN_OFF + BM * 4)       // 93184 B

// Static global scratch (no allocation allowed).
__device__ __align__(128) __nv_bfloat16 g_Xhi[(size_t)NROWS_PAD * KPADX];
__device__ __align__(128) __nv_bfloat16 g_Xlo[(size_t)NROWS_PAD * KPADX];
__device__ __align__(128) __nv_bfloat16 g_Qhi[(size_t)NPADQ * KPADX];
__device__ __align__(128) __nv_bfloat16 g_Qlo[(size_t)NPADQ * KPADX];

// ---------------- helpers --------------------------------------------------

__device__ __forceinline__ uint32_t smem_u32(const void* p) {
    uint32_t a;
    asm("{ .reg .u64 t; cvta.to.shared.u64 t, %1; cvt.u32.u64 %0, t; }"
        : "=r"(a) : "l"(p));
    return a;
}

__device__ __forceinline__ void cp16(uint32_t dst, const void* src) {
    asm volatile("cp.async.cg.shared.global [%0], [%1], 16;"
                 :: "r"(dst), "l"(src) : "memory");
}
__device__ __forceinline__ void cp_commit() {
    asm volatile("cp.async.commit_group;" ::: "memory");
}
template <int N>
__device__ __forceinline__ void cp_wait() {
    asm volatile("cp.async.wait_group %0;" :: "n"(N) : "memory");
}

__device__ __forceinline__ void ldsm_x4(uint32_t* r, uint32_t addr) {
    asm volatile("ldmatrix.sync.aligned.m8n8.x4.shared.b16 {%0,%1,%2,%3}, [%4];"
                 : "=r"(r[0]), "=r"(r[1]), "=r"(r[2]), "=r"(r[3]) : "r"(addr));
}

__device__ __forceinline__ void mma_bf16(float* c, const uint32_t* a,
                                         uint32_t b0, uint32_t b1) {
    asm volatile(
        "mma.sync.aligned.m16n8k16.row.col.f32.bf16.bf16.f32 "
        "{%0,%1,%2,%3}, {%4,%5,%6,%7}, {%8,%9}, {%0,%1,%2,%3};"
        : "+f"(c[0]), "+f"(c[1]), "+f"(c[2]), "+f"(c[3])
        : "r"(a[0]), "r"(a[1]), "r"(a[2]), "r"(a[3]), "r"(b0), "r"(b1));
}

__device__ __forceinline__ uint32_t pack_bf2(__nv_bfloat16 a, __nv_bfloat16 b) {
    __nv_bfloat162 t = __halves2bfloat162(a, b);
    return *reinterpret_cast<uint32_t*>(&t);
}

// ---------------------------------------------------------------------------
__global__ void zero_out_kernel(float* __restrict__ out, int n) {
    int i = blockIdx.x * blockDim.x + threadIdx.x;
    if (i < n) out[i] = 0.0f;
}

// ---------------------------------------------------------------------------
// Prepass: X fp32 -> (Xhi, Xlo) bf16 with K padded to 416, rows to NROWS_PAD.
// ---------------------------------------------------------------------------
__global__ __launch_bounds__(256)
void split_x_kernel(const float* __restrict__ X, int N) {
    size_t idx = (size_t)blockIdx.x * blockDim.x + threadIdx.x;
    const size_t total = (size_t)NROWS_PAD * (KPADX / 8);
    if (idx >= total) return;
    size_t row = idx / (KPADX / 8);
    int    c8  = (int)(idx % (KPADX / 8));      // 0..51
    uint4 hv = make_uint4(0u, 0u, 0u, 0u);
    uint4 lv = make_uint4(0u, 0u, 0u, 0u);
    if (row < (size_t)N && c8 < (D_DIM / 8)) {
        const float4* p = reinterpret_cast<const float4*>(X + row * D_DIM + c8 * 8);
        float4 v0 = p[0], v1 = p[1];
        float f[8] = { v0.x, v0.y, v0.z, v0.w, v1.x, v1.y, v1.z, v1.w };
        __nv_bfloat16 h[8], l[8];
        #pragma unroll
        for (int q = 0; q < 8; ++q) {
            h[q] = __float2bfloat16(f[q]);
            l[q] = __float2bfloat16(f[q] - __bfloat162float(h[q]));
        }
        hv = make_uint4(pack_bf2(h[0], h[1]), pack_bf2(h[2], h[3]),
                        pack_bf2(h[4], h[5]), pack_bf2(h[6], h[7]));
        lv = make_uint4(pack_bf2(l[0], l[1]), pack_bf2(l[2], l[3]),
                        pack_bf2(l[4], l[5]), pack_bf2(l[6], l[7]));
    }
    size_t off = row * KPADX + (size_t)c8 * 8;
    *reinterpret_cast<uint4*>(g_Xhi + off) = hv;
    *reinterpret_cast<uint4*>(g_Xlo + off) = lv;
}

// ---------------------------------------------------------------------------
// Build Q = SP^T diag(w') SP in split bf16, layout [NPADQ][KPADX], pads zero.
// ---------------------------------------------------------------------------
__global__ __launch_bounds__(256)
void build_q_kernel(const float* __restrict__ SP,
                    const float* __restrict__ W,
                    const int*  __restrict__ colseg,
                    int M) {
    __shared__ float As[32][33];
    __shared__ float Bs[32][33];

    const int a0 = blockIdx.y * 32;       // n index (< NPADQ)
    const int b0 = blockIdx.x * 32;       // k index (< KPADX)
    const int tid = threadIdx.x;
    const int ty = tid >> 4;
    const int tx = tid & 15;

    float c00 = 0.f, c01 = 0.f, c10 = 0.f, c11 = 0.f;

    for (int j0 = 0; j0 < M; j0 += 32) {
        #pragma unroll
        for (int e = tid; e < 1024; e += 256) {
            int jj  = e >> 5;
            int col = e & 31;
            int j   = j0 + jj;
            float av = 0.f, bv = 0.f;
            if (j < M) {
                float wp = W[colseg[j]];
                int a = a0 + col;
                int b = b0 + col;
                if (a < D_DIM) av = SP[(size_t)j * D_DIM + a] * wp;
                if (b < D_DIM) bv = SP[(size_t)j * D_DIM + b];
            }
            As[jj][col] = av;
            Bs[jj][col] = bv;
        }
        __syncthreads();

        #pragma unroll
        for (int jj = 0; jj < 32; ++jj) {
            float a0r = As[jj][ty];
            float a1r = As[jj][ty + 16];
            float b0r = Bs[jj][tx];
            float b1r = Bs[jj][tx + 16];
            c00 = fmaf(a0r, b0r, c00);
            c01 = fmaf(a0r, b1r, c01);
            c10 = fmaf(a1r, b0r, c10);
            c11 = fmaf(a1r, b1r, c11);
        }
        __syncthreads();
    }

    float vals[4] = { c00, c01, c10, c11 };
    int   aa[4]   = { a0 + ty, a0 + ty, a0 + ty + 16, a0 + ty + 16 };
    int   bb[4]   = { b0 + tx, b0 + tx + 16, b0 + tx, b0 + tx + 16 };
    #pragma unroll
    for (int q = 0; q < 4; ++q) {
        if (aa[q] < NPADQ && bb[q] < KPADX) {
            __nv_bfloat16 hi = __float2bfloat16(vals[q]);
            __nv_bfloat16 lo = __float2bfloat16(vals[q] - __bfloat162float(hi));
            size_t idx = (size_t)aa[q] * KPADX + bb[q];
            g_Qhi[idx] = hi;
            g_Qlo[idx] = lo;
        }
    }
}

// ---------------------------------------------------------------------------
// Main kernel: 256 threads (8 warps: 4 M-slices x 2 N-slices).
// Flat loop over 91 (nc, sl) pairs with 3-stage cp.async ring, one
// __syncthreads per slice, no drain at chunk boundaries.
// ---------------------------------------------------------------------------
__global__ __launch_bounds__(256, 2)
void gap_mma_kernel(const float* __restrict__ X,
                    const int*  __restrict__ rowseg,
                    float* __restrict__ out,
                    int N) {
    extern __shared__ __align__(16) char smem[];
    float* const sv = reinterpret_cast<float*>(smem + SV_OFF);
    float* const sn = reinterpret_cast<float*>(smem + SN_OFF);

    const int tid  = threadIdx.x;
    const int lane = tid & 31;
    const int wid  = tid >> 5;
    const int wm   = wid & 3;            // M slice 0..3 (32 rows)
    const int wn   = wid >> 2;           // N slice 0..1 (32 cols)
    const int g    = lane >> 2;
    const int tg   = lane & 3;

    const uint32_t s_u32 = smem_u32(smem);

    // ldmatrix per-lane offsets
    const int arow_l = lane & 15;
    const int acol_l = (lane >> 4) * 8;
    const int brow_l = (lane & 7) + ((lane >> 4) << 3);
    const int bcol_l = ((lane >> 3) & 1) * 8;

    const size_t row0 = (size_t)blockIdx.x * BM;

    if (tid < BM) { sv[tid] = 0.f; sn[tid] = 0.f; }

    float vp[4] = { 0.f, 0.f, 0.f, 0.f };
    float np[4] = { 0.f, 0.f, 0.f, 0.f };

    // Per-thread cp.async mapping (6 x 16B per slice)
    const int ra = tid >> 2;
    const int ca = tid & 3;
    const int rb = tid >> 2;
    const int cb = tid & 3;

    // stage slice (sl of chunk nc) into ring buffer buf
    auto stage = [&](int sl, int nc, int buf) {
        const int ks = sl * 32;
        const uint32_t sb = s_u32 + (uint32_t)buf * (STAGE_EL * 2);
        const __nv_bfloat16* Bh = g_Qhi + (size_t)(nc * BN) * KPADX;
        const __nv_bfloat16* Bl = g_Qlo + (size_t)(nc * BN) * KPADX;
        cp16(sb + (O_AHI + ra * AS_ST + ca * 8) * 2,
             g_Xhi + (row0 + ra) * KPADX + ks + ca * 8);
        cp16(sb + (O_AHI + (ra + 64) * AS_ST + ca * 8) * 2,
             g_Xhi + (row0 + ra + 64) * KPADX + ks + ca * 8);
        cp16(sb + (O_ALO + ra * AS_ST + ca * 8) * 2,
             g_Xlo + (row0 + ra) * KPADX + ks + ca * 8);
        cp16(sb + (O_ALO + (ra + 64) * AS_ST + ca * 8) * 2,
             g_Xlo + (row0 + ra + 64) * KPADX + ks + ca * 8);
        cp16(sb + (O_BHI + rb * AS_ST + cb * 8) * 2,
             Bh + (size_t)rb * KPADX + ks + cb * 8);
        cp16(sb + (O_BLO + rb * AS_ST + cb * 8) * 2,
             Bl + (size_t)rb * KPADX + ks + cb * 8);
        cp_commit();
    };

    float c[2][4][4];
    #pragma unroll
    for (int mt = 0; mt < 2; ++mt)
        #pragma unroll
        for (int nt = 0; nt < 4; ++nt)
            #pragma unroll
            for (int q = 0; q < 4; ++q) c[mt][nt][q] = 0.f;

    // prologue: stage gs=0, gs=1
    stage(0, 0, 0);
    stage(1, 0, 1);
    cp_wait<1>();
    __syncthreads();

    int sl_c = 0, nc_c = 0, buf_c = 0;   // compute cursor (gs)
    int sl_p = 2, nc_p = 0, buf_p = 2;   // prefetch cursor (gs+2)

    #pragma unroll 1
    for (int gs = 0; gs < TOTS; ++gs) {
        const bool do_stage = (gs + 2 < TOTS);
        if (do_stage) stage(sl_p, nc_p, buf_p);

        // ---- compute on buf_c ----
        const uint32_t sb = s_u32 + (uint32_t)buf_c * (STAGE_EL * 2);
        #pragma unroll
        for (int kk = 0; kk < 2; ++kk) {
            uint32_t ahi[2][4], alo[2][4], bhi[2][4], blo[2][4];
            #pragma unroll
            for (int mt = 0; mt < 2; ++mt) {
                uint32_t ao = (uint32_t)(((wm * 32 + 16 * mt + arow_l) * AS_ST
                                          + kk * 16 + acol_l) * 2);
                ldsm_x4(ahi[mt], sb + O_AHI * 2 + ao);
                ldsm_x4(alo[mt], sb + O_ALO * 2 + ao);
            }
            #pragma unroll
            for (int nh = 0; nh < 2; ++nh) {
                uint32_t bo = (uint32_t)(((wn * 32 + 16 * nh + brow_l) * AS_ST
                                          + kk * 16 + bcol_l) * 2);
                ldsm_x4(bhi[nh], sb + O_BHI * 2 + bo);
                ldsm_x4(blo[nh], sb + O_BLO * 2 + bo);
            }
            #pragma unroll
            for (int mt = 0; mt < 2; ++mt)
                #pragma unroll
                for (int nt = 0; nt < 4; ++nt) {
                    uint32_t bh0 = bhi[nt >> 1][(nt & 1) * 2];
                    uint32_t bh1 = bhi[nt >> 1][(nt & 1) * 2 + 1];
                    uint32_t bl0 = blo[nt >> 1][(nt & 1) * 2];
                    uint32_t bl1 = blo[nt >> 1][(nt & 1) * 2 + 1];
                    mma_bf16(c[mt][nt], ahi[mt], bh0, bh1);
                    mma_bf16(c[mt][nt], alo[mt], bh0, bh1);
                    mma_bf16(c[mt][nt], ahi[mt], bl0, bl1);
                }
        }

        // ---- end of chunk: fold and reset ----
        if (sl_c == NSLICE - 1) {
            #pragma unroll
            for (int mt = 0; mt < 2; ++mt) {
                const int    r0l = wm * 32 + 16 * mt + g;
                const size_t R0  = row0 + (size_t)r0l;
                #pragma unroll
                for (int nt = 0; nt < 4; ++nt) {
                    int C0 = nc_c * 64 + wn * 32 + 8 * nt + 2 * tg;
                    if (C0 < D_DIM) {
                        if (R0 < (size_t)N) {
                            float2 x0 = __ldg(reinterpret_cast<const float2*>(
                                X + R0 * D_DIM + C0));
                            vp[2 * mt] = fmaf(x0.x, c[mt][nt][0],
                                          fmaf(x0.y, c[mt][nt][1], vp[2 * mt]));
                            np[2 * mt] = fmaf(x0.x, x0.x,
                                          fmaf(x0.y, x0.y, np[2 * mt]));
                        }
                        if (R0 + 8 < (size_t)N) {
                            float2 x1 = __ldg(reinterpret_cast<const float2*>(
                                X + (R0 + 8) * D_DIM + C0));
                            vp[2 * mt + 1] = fmaf(x1.x, c[mt][nt][2],
                                              fmaf(x1.y, c[mt][nt][3], vp[2 * mt + 1]));
                            np[2 * mt + 1] = fmaf(x1.x, x1.x,
                                              fmaf(x1.y, x1.y, np[2 * mt + 1]));
                        }
                    }
                    #pragma unroll
                    for (int q = 0; q < 4; ++q) c[mt][nt][q] = 0.f;
                }
            }
        }

        if (do_stage) cp_wait<1>(); else cp_wait<0>();
        __syncthreads();

        // advance cursors
        ++buf_c; if (buf_c == NSTG) buf_c = 0;
        ++buf_p; if (buf_p == NSTG) buf_p = 0;
        ++sl_c;  if (sl_c == NSLICE) { sl_c = 0; ++nc_c; }
        ++sl_p;  if (sl_p == NSLICE) { sl_p = 0; ++nc_p; }
    }

    // reduce across the 4 lanes sharing each row, then smem accumulate
    #pragma unroll
    for (int i = 0; i < 4; ++i) {
        vp[i] += __shfl_xor_sync(0xFFFFFFFFu, vp[i], 1);
        vp[i] += __shfl_xor_sync(0xFFFFFFFFu, vp[i], 2);
        np[i] += __shfl_xor_sync(0xFFFFFFFFu, np[i], 1);
        np[i] += __shfl_xor_sync(0xFFFFFFFFu, np[i], 2);
    }
    if (tg == 0) {
        #pragma unroll
        for (int i = 0; i < 4; ++i) {
            int mt = i >> 1, hi = i & 1;
            int r  = wm * 32 + 16 * mt + 8 * hi + g;
            atomicAdd(&sv[r], vp[i]);
            atomicAdd(&sn[r], np[i]);
        }
    }
    __syncthreads();

    // one atomic per valid row into the segment output
    if (tid < BM) {
        size_t row = row0 + (size_t)tid;
        if (row < (size_t)N) {
            float nr = sn[tid];
            if (nr > 0.f)
                atomicAdd(out + __ldg(rowseg + row), sv[tid] / nr);
        }
    }
}

// ---------------------------------------------------------------------------
extern "C" void kernel_launch(void* const* d_in, const int* in_sizes, int n_in,
                              void* d_out, int out_size) {
    const float* X      = (const float*)d_in[0];
    const float* SP     = (const float*)d_in[1];
    const float* W      = (const float*)d_in[2];
    const int*   rowseg = (const int*)  d_in[4];
    const int*   colseg = (const int*)  d_in[5];
    float* out = (float*)d_out;

    const int N = in_sizes[4];   // environments
    const int M = in_sizes[5];   // support points

    zero_out_kernel<<<(out_size + 255) / 256, 256>>>(out, out_size);

    // prepass: split X into bf16 hi/lo (K padded to 416, rows to NROWS_PAD)
    {
        size_t total = (size_t)NROWS_PAD * (KPADX / 8);
        int blocks = (int)((total + 255) / 256);
        split_x_kernel<<<blocks, 256>>>(X, N);
    }

    // build split-bf16 Q
    {
        dim3 qgrid(KPADX / 32, NPADQ / 32);   // 13 x 14
        build_q_kernel<<<qgrid, 256>>>(SP, W, colseg, M);
    }

    // main fused GEMM + quadratic form + segment reduction
    cudaFuncSetAttribute(gap_mma_kernel,
                         cudaFuncAttributeMaxDynamicSharedMemorySize, SMEM_TOTAL);
    int ntiles = (N + BM - 1) / BM;
    gap_mma_kernel<<<ntiles, 256, SMEM_TOTAL>>>(X, rowseg, out, N);
}

// round 13
// speedup vs baseline: 1.2444x; 1.2444x over previous
#include <cuda_runtime.h>
#include <cuda_bf16.h>
#include <cstdint>

// ---------------------------------------------------------------------------
// FullGapModel collapse:
//   out[s] = sum_{i: row_seg[i]==s} (x_i^T Q x_i) / ||x_i||^2
//   Q[a,b] = sum_j weights[col_seg[j]] * SP[j,a] * SP[j,b]   (400x400, sym)
//
// R13: 2-product scheme using Q symmetry.
//   xh = bf16(x),  D = (Qhi + Qlo) * xh   (HMMA, fp32 accum)
//   v  = (2x - xh)^T D = x^T Q x - xl^T Q xl   (error ~ eps_bf16^2)
//   out[seg] += v / ||x||^2
// 4-stage cp.async ring, one __syncthreads per 32-wide K slice, no drains.
// ---------------------------------------------------------------------------

#define D_DIM     400
#define KPADX     416          // K padded: 13 slices of 32
#define NSLICE    13
#define NPADQ     448          // Q rows padded: 7 chunks of 64
#define NCHUNK    7
#define TOTS      (NSLICE * NCHUNK)   // 91
#define BM        128
#define BN        64
#define NROWS_PAD 100096       // 782 * 128
#define C8MAX     (KPADX / 8)  // 52

#define AS_ST     40                       // bf16 elems per smem row (32+8 pad)
#define A_EL      (BM * AS_ST)             // 5120
#define B_EL      (BN * AS_ST)             // 2560
#define O_AHI     0
#define O_BHI     A_EL
#define O_BLO     (A_EL + B_EL)
#define STAGE_EL  (A_EL + 2 * B_EL)        // 10240 elems = 20480 B
#define NSTG      4
#define SV_OFF    (NSTG * STAGE_EL * 2)    // bytes: 81920
#define SN_OFF    (SV_OFF + BM * 4)
#define SMEM_TOTAL (SN_OFF + BM * 4)       // 82944 B

// Static global scratch (no allocation allowed).
__device__ __align__(128) __nv_bfloat16 g_Xhi[(size_t)NROWS_PAD * KPADX];
__device__ __align__(128) __nv_bfloat16 g_Qhi[(size_t)NPADQ * KPADX];
__device__ __align__(128) __nv_bfloat16 g_Qlo[(size_t)NPADQ * KPADX];

// ---------------- helpers --------------------------------------------------

__device__ __forceinline__ uint32_t smem_u32(const void* p) {
    uint32_t a;
    asm("{ .reg .u64 t; cvta.to.shared.u64 t, %1; cvt.u32.u64 %0, t; }"
        : "=r"(a) : "l"(p));
    return a;
}

__device__ __forceinline__ void cp16(uint32_t dst, const void* src) {
    asm volatile("cp.async.cg.shared.global [%0], [%1], 16;"
                 :: "r"(dst), "l"(src) : "memory");
}
__device__ __forceinline__ void cp_commit() {
    asm volatile("cp.async.commit_group;" ::: "memory");
}
template <int N>
__device__ __forceinline__ void cp_wait() {
    asm volatile("cp.async.wait_group %0;" :: "n"(N) : "memory");
}

__device__ __forceinline__ void ldsm_x4(uint32_t* r, uint32_t addr) {
    asm volatile("ldmatrix.sync.aligned.m8n8.x4.shared.b16 {%0,%1,%2,%3}, [%4];"
                 : "=r"(r[0]), "=r"(r[1]), "=r"(r[2]), "=r"(r[3]) : "r"(addr));
}

__device__ __forceinline__ void mma_bf16(float* c, const uint32_t* a,
                                         uint32_t b0, uint32_t b1) {
    asm volatile(
        "mma.sync.aligned.m16n8k16.row.col.f32.bf16.bf16.f32 "
        "{%0,%1,%2,%3}, {%4,%5,%6,%7}, {%8,%9}, {%0,%1,%2,%3};"
        : "+f"(c[0]), "+f"(c[1]), "+f"(c[2]), "+f"(c[3])
        : "r"(a[0]), "r"(a[1]), "r"(a[2]), "r"(a[3]), "r"(b0), "r"(b1));
}

__device__ __forceinline__ uint32_t pack_bf2(__nv_bfloat16 a, __nv_bfloat16 b) {
    __nv_bfloat162 t = __halves2bfloat162(a, b);
    return *reinterpret_cast<uint32_t*>(&t);
}

// ---------------------------------------------------------------------------
__global__ void zero_out_kernel(float* __restrict__ out, int n) {
    int i = blockIdx.x * blockDim.x + threadIdx.x;
    if (i < n) out[i] = 0.0f;
}

// ---------------------------------------------------------------------------
// Prepass: X fp32 -> Xhi bf16 (K padded to 416, rows to NROWS_PAD).
// Divide-free indexing: 4 rows per 256-thread block, 64 threads per row.
// ---------------------------------------------------------------------------
__global__ __launch_bounds__(256)
void split_x_kernel(const float* __restrict__ X, int N) {
    const int tid = threadIdx.x;
    const int r   = blockIdx.x * 4 + (tid >> 6);
    const int c8  = tid & 63;
    if (c8 >= C8MAX || r >= NROWS_PAD) return;
    uint4 hv = make_uint4(0u, 0u, 0u, 0u);
    if (r < N && c8 < (D_DIM / 8)) {
        const float4* p = reinterpret_cast<const float4*>(
            X + (size_t)r * D_DIM + c8 * 8);
        float4 v0 = p[0], v1 = p[1];
        float f[8] = { v0.x, v0.y, v0.z, v0.w, v1.x, v1.y, v1.z, v1.w };
        __nv_bfloat16 h[8];
        #pragma unroll
        for (int q = 0; q < 8; ++q) h[q] = __float2bfloat16(f[q]);
        hv = make_uint4(pack_bf2(h[0], h[1]), pack_bf2(h[2], h[3]),
                        pack_bf2(h[4], h[5]), pack_bf2(h[6], h[7]));
    }
    *reinterpret_cast<uint4*>(g_Xhi + (size_t)r * KPADX + c8 * 8) = hv;
}

// ---------------------------------------------------------------------------
// Build Q = SP^T diag(w') SP in split bf16, layout [NPADQ][KPADX], pads zero.
// ---------------------------------------------------------------------------
__global__ __launch_bounds__(256)
void build_q_kernel(const float* __restrict__ SP,
                    const float* __restrict__ W,
                    const int*  __restrict__ colseg,
                    int M) {
    __shared__ float As[32][33];
    __shared__ float Bs[32][33];

    const int a0 = blockIdx.y * 32;       // n index (< NPADQ)
    const int b0 = blockIdx.x * 32;       // k index (< KPADX)
    const int tid = threadIdx.x;
    const int ty = tid >> 4;
    const int tx = tid & 15;

    float c00 = 0.f, c01 = 0.f, c10 = 0.f, c11 = 0.f;

    for (int j0 = 0; j0 < M; j0 += 32) {
        #pragma unroll
        for (int e = tid; e < 1024; e += 256) {
            int jj  = e >> 5;
            int col = e & 31;
            int j   = j0 + jj;
            float av = 0.f, bv = 0.f;
            if (j < M) {
                float wp = W[colseg[j]];
                int a = a0 + col;
                int b = b0 + col;
                if (a < D_DIM) av = SP[(size_t)j * D_DIM + a] * wp;
                if (b < D_DIM) bv = SP[(size_t)j * D_DIM + b];
            }
            As[jj][col] = av;
            Bs[jj][col] = bv;
        }
        __syncthreads();

        #pragma unroll
        for (int jj = 0; jj < 32; ++jj) {
            float a0r = As[jj][ty];
            float a1r = As[jj][ty + 16];
            float b0r = Bs[jj][tx];
            float b1r = Bs[jj][tx + 16];
            c00 = fmaf(a0r, b0r, c00);
            c01 = fmaf(a0r, b1r, c01);
            c10 = fmaf(a1r, b0r, c10);
            c11 = fmaf(a1r, b1r, c11);
        }
        __syncthreads();
    }

    float vals[4] = { c00, c01, c10, c11 };
    int   aa[4]   = { a0 + ty, a0 + ty, a0 + ty + 16, a0 + ty + 16 };
    int   bb[4]   = { b0 + tx, b0 + tx + 16, b0 + tx, b0 + tx + 16 };
    #pragma unroll
    for (int q = 0; q < 4; ++q) {
        if (aa[q] < NPADQ && bb[q] < KPADX) {
            __nv_bfloat16 hi = __float2bfloat16(vals[q]);
            __nv_bfloat16 lo = __float2bfloat16(vals[q] - __bfloat162float(hi));
            size_t idx = (size_t)aa[q] * KPADX + bb[q];
            g_Qhi[idx] = hi;
            g_Qlo[idx] = lo;
        }
    }
}

// ---------------------------------------------------------------------------
// Main kernel: 256 threads (8 warps: 4 M-slices x 2 N-slices).
// Flat loop over 91 (nc, sl) pairs; 4-stage cp.async ring, prefetch
// distance 3, one __syncthreads per slice, no drain at chunk boundaries.
// Per slice: 2 products (A*Bhi + A*Blo) share the staged A.
// ---------------------------------------------------------------------------
__global__ __launch_bounds__(256, 2)
void gap_mma_kernel(const float* __restrict__ X,
                    const int*  __restrict__ rowseg,
                    float* __restrict__ out,
                    int N) {
    extern __shared__ __align__(16) char smem[];
    float* const sv = reinterpret_cast<float*>(smem + SV_OFF);
    float* const sn = reinterpret_cast<float*>(smem + SN_OFF);

    const int tid  = threadIdx.x;
    const int lane = tid & 31;
    const int wid  = tid >> 5;
    const int wm   = wid & 3;            // M slice 0..3 (32 rows)
    const int wn   = wid >> 2;           // N slice 0..1 (32 cols)
    const int g    = lane >> 2;
    const int tg   = lane & 3;

    const uint32_t s_u32 = smem_u32(smem);

    // ldmatrix per-lane offsets
    const int arow_l = lane & 15;
    const int acol_l = (lane >> 4) * 8;
    const int brow_l = (lane & 7) + ((lane >> 4) << 3);
    const int bcol_l = ((lane >> 3) & 1) * 8;

    const size_t row0 = (size_t)blockIdx.x * BM;

    if (tid < BM) { sv[tid] = 0.f; sn[tid] = 0.f; }

    float vp[4] = { 0.f, 0.f, 0.f, 0.f };
    float np[4] = { 0.f, 0.f, 0.f, 0.f };

    // Per-thread cp.async mapping (4 x 16B per slice)
    const int ra = tid >> 2;
    const int ca = tid & 3;

    // stage slice (sl of chunk nc) into ring buffer buf
    auto stage = [&](int sl, int nc, int buf) {
        const int ks = sl * 32;
        const uint32_t sb = s_u32 + (uint32_t)buf * (STAGE_EL * 2);
        const __nv_bfloat16* Bh = g_Qhi + (size_t)(nc * BN) * KPADX;
        const __nv_bfloat16* Bl = g_Qlo + (size_t)(nc * BN) * KPADX;
        cp16(sb + (O_AHI + ra * AS_ST + ca * 8) * 2,
             g_Xhi + (row0 + ra) * KPADX + ks + ca * 8);
        cp16(sb + (O_AHI + (ra + 64) * AS_ST + ca * 8) * 2,
             g_Xhi + (row0 + ra + 64) * KPADX + ks + ca * 8);
        cp16(sb + (O_BHI + ra * AS_ST + ca * 8) * 2,
             Bh + (size_t)ra * KPADX + ks + ca * 8);
        cp16(sb + (O_BLO + ra * AS_ST + ca * 8) * 2,
             Bl + (size_t)ra * KPADX + ks + ca * 8);
        cp_commit();
    };

    float c[2][4][4];
    #pragma unroll
    for (int mt = 0; mt < 2; ++mt)
        #pragma unroll
        for (int nt = 0; nt < 4; ++nt)
            #pragma unroll
            for (int q = 0; q < 4; ++q) c[mt][nt][q] = 0.f;

    // prologue: stage gs=0,1,2 into bufs 0,1,2
    stage(0, 0, 0);
    stage(1, 0, 1);
    stage(2, 0, 2);
    cp_wait<2>();
    __syncthreads();

    int sl_c = 0, nc_c = 0, buf_c = 0;   // compute cursor (gs)
    int sl_p = 3, nc_p = 0, buf_p = 3;   // prefetch cursor (gs+3)

    #pragma unroll 1
    for (int gs = 0; gs < TOTS; ++gs) {
        const bool do_stage = (gs + 3 < TOTS);
        if (do_stage) stage(sl_p, nc_p, buf_p);

        // ---- compute on buf_c ----
        const uint32_t sb = s_u32 + (uint32_t)buf_c * (STAGE_EL * 2);
        #pragma unroll
        for (int kk = 0; kk < 2; ++kk) {
            uint32_t ahi[2][4], bhi[2][4], blo[2][4];
            #pragma unroll
            for (int mt = 0; mt < 2; ++mt) {
                uint32_t ao = (uint32_t)(((wm * 32 + 16 * mt + arow_l) * AS_ST
                                          + kk * 16 + acol_l) * 2);
                ldsm_x4(ahi[mt], sb + O_AHI * 2 + ao);
            }
            #pragma unroll
            for (int nh = 0; nh < 2; ++nh) {
                uint32_t bo = (uint32_t)(((wn * 32 + 16 * nh + brow_l) * AS_ST
                                          + kk * 16 + bcol_l) * 2);
                ldsm_x4(bhi[nh], sb + O_BHI * 2 + bo);
                ldsm_x4(blo[nh], sb + O_BLO * 2 + bo);
            }
            #pragma unroll
            for (int mt = 0; mt < 2; ++mt)
                #pragma unroll
                for (int nt = 0; nt < 4; ++nt) {
                    uint32_t bh0 = bhi[nt >> 1][(nt & 1) * 2];
                    uint32_t bh1 = bhi[nt >> 1][(nt & 1) * 2 + 1];
                    uint32_t bl0 = blo[nt >> 1][(nt & 1) * 2];
                    uint32_t bl1 = blo[nt >> 1][(nt & 1) * 2 + 1];
                    mma_bf16(c[mt][nt], ahi[mt], bh0, bh1);
                    mma_bf16(c[mt][nt], ahi[mt], bl0, bl1);
                }
        }

        // ---- end of chunk: fold with u = 2x - bf16(x), reset accum ----
        if (sl_c == NSLICE - 1) {
            #pragma unroll
            for (int mt = 0; mt < 2; ++mt) {
                const int    r0l = wm * 32 + 16 * mt + g;
                const size_t R0  = row0 + (size_t)r0l;
                #pragma unroll
                for (int nt = 0; nt < 4; ++nt) {
                    int C0 = nc_c * 64 + wn * 32 + 8 * nt + 2 * tg;
                    if (C0 < D_DIM) {
                        if (R0 < (size_t)N) {
                            float2 x0 = __ldg(reinterpret_cast<const float2*>(
                                X + R0 * D_DIM + C0));
                            float u0x = 2.f * x0.x -
                                __bfloat162float(__float2bfloat16(x0.x));
                            float u0y = 2.f * x0.y -
                                __bfloat162float(__float2bfloat16(x0.y));
                            vp[2 * mt] = fmaf(u0x, c[mt][nt][0],
                                          fmaf(u0y, c[mt][nt][1], vp[2 * mt]));
                            np[2 * mt] = fmaf(x0.x, x0.x,
                                          fmaf(x0.y, x0.y, np[2 * mt]));
                        }
                        if (R0 + 8 < (size_t)N) {
                            float2 x1 = __ldg(reinterpret_cast<const float2*>(
                                X + (R0 + 8) * D_DIM + C0));
                            float u1x = 2.f * x1.x -
                                __bfloat162float(__float2bfloat16(x1.x));
                            float u1y = 2.f * x1.y -
                                __bfloat162float(__float2bfloat16(x1.y));
                            vp[2 * mt + 1] = fmaf(u1x, c[mt][nt][2],
                                              fmaf(u1y, c[mt][nt][3], vp[2 * mt + 1]));
                            np[2 * mt + 1] = fmaf(x1.x, x1.x,
                                              fmaf(x1.y, x1.y, np[2 * mt + 1]));
                        }
                    }
                    #pragma unroll
                    for (int q = 0; q < 4; ++q) c[mt][nt][q] = 0.f;
                }
            }
        }

        // ---- wait for buf gs+1 and publish this iteration's staging ----
        if (gs + 3 < TOTS)      cp_wait<2>();
        else if (gs + 2 < TOTS) cp_wait<1>();
        else                    cp_wait<0>();
        __syncthreads();

        // advance cursors
        ++buf_c; if (buf_c == NSTG) buf_c = 0;
        ++buf_p; if (buf_p == NSTG) buf_p = 0;
        ++sl_c;  if (sl_c == NSLICE) { sl_c = 0; ++nc_c; }
        ++sl_p;  if (sl_p == NSLICE) { sl_p = 0; ++nc_p; }
    }

    // reduce across the 4 lanes sharing each row, then smem accumulate
    #pragma unroll
    for (int i = 0; i < 4; ++i) {
        vp[i] += __shfl_xor_sync(0xFFFFFFFFu, vp[i], 1);
        vp[i] += __shfl_xor_sync(0xFFFFFFFFu, vp[i], 2);
        np[i] += __shfl_xor_sync(0xFFFFFFFFu, np[i], 1);
        np[i] += __shfl_xor_sync(0xFFFFFFFFu, np[i], 2);
    }
    if (tg == 0) {
        #pragma unroll
        for (int i = 0; i < 4; ++i) {
            int mt = i >> 1, hi = i & 1;
            int r  = wm * 32 + 16 * mt + 8 * hi + g;
            atomicAdd(&sv[r], vp[i]);
            atomicAdd(&sn[r], np[i]);
        }
    }
    __syncthreads();

    // one atomic per valid row into the segment output
    if (tid < BM) {
        size_t row = row0 + (size_t)tid;
        if (row < (size_t)N) {
            float nr = sn[tid];
            if (nr > 0.f)
                atomicAdd(out + __ldg(rowseg + row), sv[tid] / nr);
        }
    }
}

// ---------------------------------------------------------------------------
extern "C" void kernel_launch(void* const* d_in, const int* in_sizes, int n_in,
                              void* d_out, int out_size) {
    const float* X      = (const float*)d_in[0];
    const float* SP     = (const float*)d_in[1];
    const float* W      = (const float*)d_in[2];
    const int*   rowseg = (const int*)  d_in[4];
    const int*   colseg = (const int*)  d_in[5];
    float* out = (float*)d_out;

    const int N = in_sizes[4];   // environments
    const int M = in_sizes[5];   // support points

    zero_out_kernel<<<(out_size + 255) / 256, 256>>>(out, out_size);

    // prepass: X -> bf16 Xhi (K padded to 416, rows to NROWS_PAD)
    split_x_kernel<<<NROWS_PAD / 4, 256>>>(X, N);

    // build split-bf16 Q
    {
        dim3 qgrid(KPADX / 32, NPADQ / 32);   // 13 x 14
        build_q_kernel<<<qgrid, 256>>>(SP, W, colseg, M);
    }

    // main fused GEMM + quadratic form + segment reduction
    cudaFuncSetAttribute(gap_mma_kernel,
                         cudaFuncAttributeMaxDynamicSharedMemorySize, SMEM_TOTAL);
    int ntiles = (N + BM - 1) / BM;
    gap_mma_kernel<<<ntiles, 256, SMEM_TOTAL>>>(X, rowseg, out, N);
}

// round 14
// speedup vs baseline: 1.5890x; 1.2769x over previous
#include <cuda_runtime.h>
#include <cuda_bf16.h>
#include <cstdint>

// ---------------------------------------------------------------------------
// FullGapModel collapse:
//   out[s] = sum_{i: row_seg[i]==s} (x_i^T Q x_i) / ||x_i||^2
//   Q[a,b] = sum_j weights[col_seg[j]] * SP[j,a] * SP[j,b]   (400x400, sym)
//
// 2-product scheme using Q symmetry (R13):
//   xh = bf16(x),  D = (Qhi + Qlo) * xh   (HMMA, fp32 accum)
//   v  = (2x - xh)^T D = x^T Q x - xl^T Q xl   (error ~ eps_bf16^2)
// R14: prepass restructured —
//   prep kernel  = { 1456 build-Q blocks (K-split x8, fp32 partials)
//                    25024 split-X blocks }  running CONCURRENTLY
//   convert_q    = sum partials -> split bf16 Q, + zero output
//   gap_mma      = unchanged from R13.
// ---------------------------------------------------------------------------

#define D_DIM     400
#define KPADX     416          // K padded: 13 slices of 32
#define NSLICE    13
#define NPADQ     448          // Q padded rows: 7 chunks of 64
#define NCHUNK    7
#define TOTS      (NSLICE * NCHUNK)   // 91
#define BM        128
#define BN        64
#define NROWS_PAD 100096       // 782 * 128
#define C8MAX     (KPADX / 8)  // 52

#define QTILES    (13 * 14)    // 182 (k-tiles x n-tiles)
#define KSPLIT    8
#define NQB       (QTILES * KSPLIT)   // 1456 build blocks
#define NSB       (NROWS_PAD / 4)     // 25024 split blocks

#define AS_ST     40                       // bf16 elems per smem row (32+8 pad)
#define A_EL      (BM * AS_ST)             // 5120
#define B_EL      (BN * AS_ST)             // 2560
#define O_AHI     0
#define O_BHI     A_EL
#define O_BLO     (A_EL + B_EL)
#define STAGE_EL  (A_EL + 2 * B_EL)        // 10240 elems = 20480 B
#define NSTG      4
#define SV_OFF    (NSTG * STAGE_EL * 2)    // bytes: 81920
#define SN_OFF    (SV_OFF + BM * 4)
#define SMEM_TOTAL (SN_OFF + BM * 4)       // 82944 B

// Static global scratch (no allocation allowed).
__device__ __align__(128) __nv_bfloat16 g_Xhi[(size_t)NROWS_PAD * KPADX];
__device__ __align__(128) __nv_bfloat16 g_Qhi[(size_t)NPADQ * KPADX];
__device__ __align__(128) __nv_bfloat16 g_Qlo[(size_t)NPADQ * KPADX];
__device__ __align__(128) float g_Qpart[(size_t)KSPLIT * NPADQ * KPADX];

// ---------------- helpers --------------------------------------------------

__device__ __forceinline__ uint32_t smem_u32(const void* p) {
    uint32_t a;
    asm("{ .reg .u64 t; cvta.to.shared.u64 t, %1; cvt.u32.u64 %0, t; }"
        : "=r"(a) : "l"(p));
    return a;
}

__device__ __forceinline__ void cp16(uint32_t dst, const void* src) {
    asm volatile("cp.async.cg.shared.global [%0], [%1], 16;"
                 :: "r"(dst), "l"(src) : "memory");
}
__device__ __forceinline__ void cp_commit() {
    asm volatile("cp.async.commit_group;" ::: "memory");
}
template <int N>
__device__ __forceinline__ void cp_wait() {
    asm volatile("cp.async.wait_group %0;" :: "n"(N) : "memory");
}

__device__ __forceinline__ void ldsm_x4(uint32_t* r, uint32_t addr) {
    asm volatile("ldmatrix.sync.aligned.m8n8.x4.shared.b16 {%0,%1,%2,%3}, [%4];"
                 : "=r"(r[0]), "=r"(r[1]), "=r"(r[2]), "=r"(r[3]) : "r"(addr));
}

__device__ __forceinline__ void mma_bf16(float* c, const uint32_t* a,
                                         uint32_t b0, uint32_t b1) {
    asm volatile(
        "mma.sync.aligned.m16n8k16.row.col.f32.bf16.bf16.f32 "
        "{%0,%1,%2,%3}, {%4,%5,%6,%7}, {%8,%9}, {%0,%1,%2,%3};"
        : "+f"(c[0]), "+f"(c[1]), "+f"(c[2]), "+f"(c[3])
        : "r"(a[0]), "r"(a[1]), "r"(a[2]), "r"(a[3]), "r"(b0), "r"(b1));
}

__device__ __forceinline__ uint32_t pack_bf2(__nv_bfloat16 a, __nv_bfloat16 b) {
    __nv_bfloat162 t = __halves2bfloat162(a, b);
    return *reinterpret_cast<uint32_t*>(&t);
}

// ---------------------------------------------------------------------------
// prep kernel: blocks [0, NQB) build Q partials (K-split x8);
//              blocks [NQB, NQB+NSB) split X -> bf16. The two halves are
//              independent and overlap on the machine.
// ---------------------------------------------------------------------------
__global__ __launch_bounds__(256)
void prep_kernel(const float* __restrict__ X,
                 const float* __restrict__ SP,
                 const float* __restrict__ W,
                 const int*  __restrict__ colseg,
                 int N, int M) {
    __shared__ float As[32][33];
    __shared__ float Bs[32][33];

    const int tid = threadIdx.x;

    if (blockIdx.x < NQB) {
        // ---------------- build-Q partial ----------------
        const int bq    = blockIdx.x;
        const int tile  = bq % QTILES;
        const int chunk = bq / QTILES;
        const int bx    = tile % 13;          // k tile
        const int by    = tile / 13;          // n tile
        const int a0    = by * 32;
        const int b0    = bx * 32;
        const int ty    = tid >> 4;
        const int tx    = tid & 15;

        const int csz  = (M + KSPLIT - 1) / KSPLIT;
        const int jbeg = chunk * csz;
        const int jend = (jbeg + csz < M) ? (jbeg + csz) : M;

        float c00 = 0.f, c01 = 0.f, c10 = 0.f, c11 = 0.f;

        for (int j0 = jbeg; j0 < jend; j0 += 32) {
            #pragma unroll
            for (int e = tid; e < 1024; e += 256) {
                int jj  = e >> 5;
                int col = e & 31;
                int j   = j0 + jj;
                float av = 0.f, bv = 0.f;
                if (j < jend) {
                    float wp = W[colseg[j]];
                    int a = a0 + col;
                    int b = b0 + col;
                    if (a < D_DIM) av = SP[(size_t)j * D_DIM + a] * wp;
                    if (b < D_DIM) bv = SP[(size_t)j * D_DIM + b];
                }
                As[jj][col] = av;
                Bs[jj][col] = bv;
            }
            __syncthreads();

            #pragma unroll
            for (int jj = 0; jj < 32; ++jj) {
                float a0r = As[jj][ty];
                float a1r = As[jj][ty + 16];
                float b0r = Bs[jj][tx];
                float b1r = Bs[jj][tx + 16];
                c00 = fmaf(a0r, b0r, c00);
                c01 = fmaf(a0r, b1r, c01);
                c10 = fmaf(a1r, b0r, c10);
                c11 = fmaf(a1r, b1r, c11);
            }
            __syncthreads();
        }

        float* qp = g_Qpart + (size_t)chunk * (NPADQ * KPADX);
        qp[(size_t)(a0 + ty     ) * KPADX + (b0 + tx     )] = c00;
        qp[(size_t)(a0 + ty     ) * KPADX + (b0 + tx + 16)] = c01;
        qp[(size_t)(a0 + ty + 16) * KPADX + (b0 + tx     )] = c10;
        qp[(size_t)(a0 + ty + 16) * KPADX + (b0 + tx + 16)] = c11;
    } else {
        // ---------------- split X -> bf16 ----------------
        const int bs = blockIdx.x - NQB;
        const int r  = bs * 4 + (tid >> 6);
        const int c8 = tid & 63;
        if (c8 >= C8MAX || r >= NROWS_PAD) return;
        uint4 hv = make_uint4(0u, 0u, 0u, 0u);
        if (r < N && c8 < (D_DIM / 8)) {
            const float4* p = reinterpret_cast<const float4*>(
                X + (size_t)r * D_DIM + c8 * 8);
            float4 v0 = p[0], v1 = p[1];
            float f[8] = { v0.x, v0.y, v0.z, v0.w, v1.x, v1.y, v1.z, v1.w };
            __nv_bfloat16 h[8];
            #pragma unroll
            for (int q = 0; q < 8; ++q) h[q] = __float2bfloat16(f[q]);
            hv = make_uint4(pack_bf2(h[0], h[1]), pack_bf2(h[2], h[3]),
                            pack_bf2(h[4], h[5]), pack_bf2(h[6], h[7]));
        }
        *reinterpret_cast<uint4*>(g_Xhi + (size_t)r * KPADX + c8 * 8) = hv;
    }
}

// ---------------------------------------------------------------------------
// convert_q: sum the 8 fp32 partials -> split bf16 Qhi/Qlo. Block 0 also
// zeroes the output vector (harness poisons it with 0xAA).
// Grid: NPADQ blocks of KPADX threads.
// ---------------------------------------------------------------------------
__global__ __launch_bounds__(KPADX)
void convert_q_kernel(float* __restrict__ out, int nout) {
    const int a = blockIdx.x;     // 0..447
    const int b = threadIdx.x;    // 0..415
    float s = 0.f;
    #pragma unroll
    for (int c = 0; c < KSPLIT; ++c)
        s += g_Qpart[(size_t)c * (NPADQ * KPADX) + (size_t)a * KPADX + b];
    __nv_bfloat16 hi = __float2bfloat16(s);
    __nv_bfloat16 lo = __float2bfloat16(s - __bfloat162float(hi));
    const size_t idx = (size_t)a * KPADX + b;
    g_Qhi[idx] = hi;
    g_Qlo[idx] = lo;
    if (blockIdx.x == 0)
        for (int i = b; i < nout; i += KPADX) out[i] = 0.f;
}

// ---------------------------------------------------------------------------
// Main kernel (unchanged from R13): 256 threads (8 warps: 4Mx2N slices),
// flat loop over 91 (nc, sl) pairs, 4-stage cp.async ring, prefetch
// distance 3, one __syncthreads per slice, no drains.
// ---------------------------------------------------------------------------
__global__ __launch_bounds__(256, 2)
void gap_mma_kernel(const float* __restrict__ X,
                    const int*  __restrict__ rowseg,
                    float* __restrict__ out,
                    int N) {
    extern __shared__ __align__(16) char smem[];
    float* const sv = reinterpret_cast<float*>(smem + SV_OFF);
    float* const sn = reinterpret_cast<float*>(smem + SN_OFF);

    const int tid  = threadIdx.x;
    const int lane = tid & 31;
    const int wid  = tid >> 5;
    const int wm   = wid & 3;            // M slice 0..3 (32 rows)
    const int wn   = wid >> 2;           // N slice 0..1 (32 cols)
    const int g    = lane >> 2;
    const int tg   = lane & 3;

    const uint32_t s_u32 = smem_u32(smem);

    const int arow_l = lane & 15;
    const int acol_l = (lane >> 4) * 8;
    const int brow_l = (lane & 7) + ((lane >> 4) << 3);
    const int bcol_l = ((lane >> 3) & 1) * 8;

    const size_t row0 = (size_t)blockIdx.x * BM;

    if (tid < BM) { sv[tid] = 0.f; sn[tid] = 0.f; }

    float vp[4] = { 0.f, 0.f, 0.f, 0.f };
    float np[4] = { 0.f, 0.f, 0.f, 0.f };

    const int ra = tid >> 2;
    const int ca = tid & 3;

    auto stage = [&](int sl, int nc, int buf) {
        const int ks = sl * 32;
        const uint32_t sb = s_u32 + (uint32_t)buf * (STAGE_EL * 2);
        const __nv_bfloat16* Bh = g_Qhi + (size_t)(nc * BN) * KPADX;
        const __nv_bfloat16* Bl = g_Qlo + (size_t)(nc * BN) * KPADX;
        cp16(sb + (O_AHI + ra * AS_ST + ca * 8) * 2,
             g_Xhi + (row0 + ra) * KPADX + ks + ca * 8);
        cp16(sb + (O_AHI + (ra + 64) * AS_ST + ca * 8) * 2,
             g_Xhi + (row0 + ra + 64) * KPADX + ks + ca * 8);
        cp16(sb + (O_BHI + ra * AS_ST + ca * 8) * 2,
             Bh + (size_t)ra * KPADX + ks + ca * 8);
        cp16(sb + (O_BLO + ra * AS_ST + ca * 8) * 2,
             Bl + (size_t)ra * KPADX + ks + ca * 8);
        cp_commit();
    };

    float c[2][4][4];
    #pragma unroll
    for (int mt = 0; mt < 2; ++mt)
        #pragma unroll
        for (int nt = 0; nt < 4; ++nt)
            #pragma unroll
            for (int q = 0; q < 4; ++q) c[mt][nt][q] = 0.f;

    stage(0, 0, 0);
    stage(1, 0, 1);
    stage(2, 0, 2);
    cp_wait<2>();
    __syncthreads();

    int sl_c = 0, nc_c = 0, buf_c = 0;
    int sl_p = 3, nc_p = 0, buf_p = 3;

    #pragma unroll 1
    for (int gs = 0; gs < TOTS; ++gs) {
        const bool do_stage = (gs + 3 < TOTS);
        if (do_stage) stage(sl_p, nc_p, buf_p);

        const uint32_t sb = s_u32 + (uint32_t)buf_c * (STAGE_EL * 2);
        #pragma unroll
        for (int kk = 0; kk < 2; ++kk) {
            uint32_t ahi[2][4], bhi[2][4], blo[2][4];
            #pragma unroll
            for (int mt = 0; mt < 2; ++mt) {
                uint32_t ao = (uint32_t)(((wm * 32 + 16 * mt + arow_l) * AS_ST
                                          + kk * 16 + acol_l) * 2);
                ldsm_x4(ahi[mt], sb + O_AHI * 2 + ao);
            }
            #pragma unroll
            for (int nh = 0; nh < 2; ++nh) {
                uint32_t bo = (uint32_t)(((wn * 32 + 16 * nh + brow_l) * AS_ST
                                          + kk * 16 + bcol_l) * 2);
                ldsm_x4(bhi[nh], sb + O_BHI * 2 + bo);
                ldsm_x4(blo[nh], sb + O_BLO * 2 + bo);
            }
            #pragma unroll
            for (int mt = 0; mt < 2; ++mt)
                #pragma unroll
                for (int nt = 0; nt < 4; ++nt) {
                    uint32_t bh0 = bhi[nt >> 1][(nt & 1) * 2];
                    uint32_t bh1 = bhi[nt >> 1][(nt & 1) * 2 + 1];
                    uint32_t bl0 = blo[nt >> 1][(nt & 1) * 2];
                    uint32_t bl1 = blo[nt >> 1][(nt & 1) * 2 + 1];
                    mma_bf16(c[mt][nt], ahi[mt], bh0, bh1);
                    mma_bf16(c[mt][nt], ahi[mt], bl0, bl1);
                }
        }

        if (sl_c == NSLICE - 1) {
            #pragma unroll
            for (int mt = 0; mt < 2; ++mt) {
                const int    r0l = wm * 32 + 16 * mt + g;
                const size_t R0  = row0 + (size_t)r0l;
                #pragma unroll
                for (int nt = 0; nt < 4; ++nt) {
                    int C0 = nc_c * 64 + wn * 32 + 8 * nt + 2 * tg;
                    if (C0 < D_DIM) {
                        if (R0 < (size_t)N) {
                            float2 x0 = __ldg(reinterpret_cast<const float2*>(
                                X + R0 * D_DIM + C0));
                            float u0x = 2.f * x0.x -
                                __bfloat162float(__float2bfloat16(x0.x));
                            float u0y = 2.f * x0.y -
                                __bfloat162float(__float2bfloat16(x0.y));
                            vp[2 * mt] = fmaf(u0x, c[mt][nt][0],
                                          fmaf(u0y, c[mt][nt][1], vp[2 * mt]));
                            np[2 * mt] = fmaf(x0.x, x0.x,
                                          fmaf(x0.y, x0.y, np[2 * mt]));
                        }
                        if (R0 + 8 < (size_t)N) {
                            float2 x1 = __ldg(reinterpret_cast<const float2*>(
                                X + (R0 + 8) * D_DIM + C0));
                            float u1x = 2.f * x1.x -
                                __bfloat162float(__float2bfloat16(x1.x));
                            float u1y = 2.f * x1.y -
                                __bfloat162float(__float2bfloat16(x1.y));
                            vp[2 * mt + 1] = fmaf(u1x, c[mt][nt][2],
                                              fmaf(u1y, c[mt][nt][3], vp[2 * mt + 1]));
                            np[2 * mt + 1] = fmaf(x1.x, x1.x,
                                              fmaf(x1.y, x1.y, np[2 * mt + 1]));
                        }
                    }
                    #pragma unroll
                    for (int q = 0; q < 4; ++q) c[mt][nt][q] = 0.f;
                }
            }
        }

        if (gs + 3 < TOTS)      cp_wait<2>();
        else if (gs + 2 < TOTS) cp_wait<1>();
        else                    cp_wait<0>();
        __syncthreads();

        ++buf_c; if (buf_c == NSTG) buf_c = 0;
        ++buf_p; if (buf_p == NSTG) buf_p = 0;
        ++sl_c;  if (sl_c == NSLICE) { sl_c = 0; ++nc_c; }
        ++sl_p;  if (sl_p == NSLICE) { sl_p = 0; ++nc_p; }
    }

    #pragma unroll
    for (int i = 0; i < 4; ++i) {
        vp[i] += __shfl_xor_sync(0xFFFFFFFFu, vp[i], 1);
        vp[i] += __shfl_xor_sync(0xFFFFFFFFu, vp[i], 2);
        np[i] += __shfl_xor_sync(0xFFFFFFFFu, np[i], 1);
        np[i] += __shfl_xor_sync(0xFFFFFFFFu, np[i], 2);
    }
    if (tg == 0) {
        #pragma unroll
        for (int i = 0; i < 4; ++i) {
            int mt = i >> 1, hi = i & 1;
            int r  = wm * 32 + 16 * mt + 8 * hi + g;
            atomicAdd(&sv[r], vp[i]);
            atomicAdd(&sn[r], np[i]);
        }
    }
    __syncthreads();

    if (tid < BM) {
        size_t row = row0 + (size_t)tid;
        if (row < (size_t)N) {
            float nr = sn[tid];
            if (nr > 0.f)
                atomicAdd(out + __ldg(rowseg + row), sv[tid] / nr);
        }
    }
}

// ---------------------------------------------------------------------------
extern "C" void kernel_launch(void* const* d_in, const int* in_sizes, int n_in,
                              void* d_out, int out_size) {
    const float* X      = (const float*)d_in[0];
    const float* SP     = (const float*)d_in[1];
    const float* W      = (const float*)d_in[2];
    const int*   rowseg = (const int*)  d_in[4];
    const int*   colseg = (const int*)  d_in[5];
    float* out = (float*)d_out;

    const int N = in_sizes[4];   // environments
    const int M = in_sizes[5];   // support points

    // 1) fused prepass: build-Q partials (first) + X split (rest), concurrent
    prep_kernel<<<NQB + NSB, 256>>>(X, SP, W, colseg, N, M);

    // 2) reduce Q partials -> split bf16; also zero the output vector
    convert_q_kernel<<<NPADQ, KPADX>>>(out, out_size);

    // 3) main fused GEMM + quadratic form + segment reduction
    cudaFuncSetAttribute(gap_mma_kernel,
                         cudaFuncAttributeMaxDynamicSharedMemorySize, SMEM_TOTAL);
    int ntiles = (N + BM - 1) / BM;
    gap_mma_kernel<<<ntiles, 256, SMEM_TOTAL>>>(X, rowseg, out, N);
}

// round 15
// speedup vs baseline: 2.0080x; 1.2637x over previous
#include <cuda_runtime.h>
#include <cuda_fp16.h>
#include <cstdint>

// ---------------------------------------------------------------------------
// FullGapModel collapse:
//   out[s] = sum_{i: row_seg[i]==s} (x_i^T Q x_i) / ||x_i||^2
//   Q[a,b] = sum_j weights[col_seg[j]] * SP[j,a] * SP[j,b]   (400x400, sym)
//
// R15: SINGLE-product fp16 scheme (Q symmetry + fold trick):
//   xh = fp16(x),  Qf = fp16(Q),  D = Qf * xh   (HMMA fp16, fp32 accum)
//   v  = (2x - xh)^T D  =  x^T Q x - xl^T Q xl + O(eps_Q first order)
//   fp16 RN residues are zero-mean -> error averages to ~1e-4 rel, gate 1e-3.
// Pipeline: flat 91-slice loop, 5-stage cp.async ring, prefetch distance 4,
// one __syncthreads per slice, no drains (structure proven in R13/R14).
// ---------------------------------------------------------------------------

#define D_DIM     400
#define KPADX     416          // K padded: 13 slices of 32
#define NSLICE    13
#define NPADQ     448          // Q padded rows: 7 chunks of 64
#define NCHUNK    7
#define TOTS      (NSLICE * NCHUNK)   // 91
#define BM        128
#define BN        64
#define NROWS_PAD 100096       // 782 * 128
#define C8MAX     (KPADX / 8)  // 52

#define QTILES    (13 * 14)    // 182 (k-tiles x n-tiles)
#define KSPLIT    8
#define NQB       (QTILES * KSPLIT)   // 1456 build blocks
#define NSB       (NROWS_PAD / 4)     // 25024 split blocks

#define AS_ST     40                       // fp16 elems per smem row (32+8 pad)
#define A_EL      (BM * AS_ST)             // 5120
#define B_EL      (BN * AS_ST)             // 2560
#define O_AHI     0
#define O_BHI     A_EL
#define STAGE_EL  (A_EL + B_EL)            // 7680 elems = 15360 B
#define NSTG      5
#define SV_OFF    (NSTG * STAGE_EL * 2)    // bytes: 76800
#define SN_OFF    (SV_OFF + BM * 4)
#define SMEM_TOTAL (SN_OFF + BM * 4)       // 77824 B

// Static global scratch (no allocation allowed).
__device__ __align__(128) __half g_Xh[(size_t)NROWS_PAD * KPADX];
__device__ __align__(128) __half g_Qh[(size_t)NPADQ * KPADX];
__device__ __align__(128) float  g_Qpart[(size_t)KSPLIT * NPADQ * KPADX];

// ---------------- helpers --------------------------------------------------

__device__ __forceinline__ uint32_t smem_u32(const void* p) {
    uint32_t a;
    asm("{ .reg .u64 t; cvta.to.shared.u64 t, %1; cvt.u32.u64 %0, t; }"
        : "=r"(a) : "l"(p));
    return a;
}

__device__ __forceinline__ void cp16(uint32_t dst, const void* src) {
    asm volatile("cp.async.cg.shared.global [%0], [%1], 16;"
                 :: "r"(dst), "l"(src) : "memory");
}
__device__ __forceinline__ void cp_commit() {
    asm volatile("cp.async.commit_group;" ::: "memory");
}
template <int N>
__device__ __forceinline__ void cp_wait() {
    asm volatile("cp.async.wait_group %0;" :: "n"(N) : "memory");
}

__device__ __forceinline__ void ldsm_x4(uint32_t* r, uint32_t addr) {
    asm volatile("ldmatrix.sync.aligned.m8n8.x4.shared.b16 {%0,%1,%2,%3}, [%4];"
                 : "=r"(r[0]), "=r"(r[1]), "=r"(r[2]), "=r"(r[3]) : "r"(addr));
}

__device__ __forceinline__ void mma_f16(float* c, const uint32_t* a,
                                        uint32_t b0, uint32_t b1) {
    asm volatile(
        "mma.sync.aligned.m16n8k16.row.col.f32.f16.f16.f32 "
        "{%0,%1,%2,%3}, {%4,%5,%6,%7}, {%8,%9}, {%0,%1,%2,%3};"
        : "+f"(c[0]), "+f"(c[1]), "+f"(c[2]), "+f"(c[3])
        : "r"(a[0]), "r"(a[1]), "r"(a[2]), "r"(a[3]), "r"(b0), "r"(b1));
}

__device__ __forceinline__ uint32_t pack_h2(__half a, __half b) {
    __half2 t = __halves2half2(a, b);   // a in low 16 bits
    return *reinterpret_cast<uint32_t*>(&t);
}

// ---------------------------------------------------------------------------
// prep kernel: blocks [0, NQB) build Q fp32 partials (K-split x8);
//              blocks [NQB, NQB+NSB) convert X -> fp16. Halves overlap.
// ---------------------------------------------------------------------------
__global__ __launch_bounds__(256)
void prep_kernel(const float* __restrict__ X,
                 const float* __restrict__ SP,
                 const float* __restrict__ W,
                 const int*  __restrict__ colseg,
                 int N, int M) {
    __shared__ float As[32][33];
    __shared__ float Bs[32][33];

    const int tid = threadIdx.x;

    if (blockIdx.x < NQB) {
        // ---------------- build-Q partial ----------------
        const int bq    = blockIdx.x;
        const int tile  = bq % QTILES;
        const int chunk = bq / QTILES;
        const int bx    = tile % 13;          // k tile
        const int by    = tile / 13;          // n tile
        const int a0    = by * 32;
        const int b0    = bx * 32;
        const int ty    = tid >> 4;
        const int tx    = tid & 15;

        const int csz  = (M + KSPLIT - 1) / KSPLIT;
        const int jbeg = chunk * csz;
        const int jend = (jbeg + csz < M) ? (jbeg + csz) : M;

        float c00 = 0.f, c01 = 0.f, c10 = 0.f, c11 = 0.f;

        for (int j0 = jbeg; j0 < jend; j0 += 32) {
            #pragma unroll
            for (int e = tid; e < 1024; e += 256) {
                int jj  = e >> 5;
                int col = e & 31;
                int j   = j0 + jj;
                float av = 0.f, bv = 0.f;
                if (j < jend) {
                    float wp = W[colseg[j]];
                    int a = a0 + col;
                    int b = b0 + col;
                    if (a < D_DIM) av = SP[(size_t)j * D_DIM + a] * wp;
                    if (b < D_DIM) bv = SP[(size_t)j * D_DIM + b];
                }
                As[jj][col] = av;
                Bs[jj][col] = bv;
            }
            __syncthreads();

            #pragma unroll
            for (int jj = 0; jj < 32; ++jj) {
                float a0r = As[jj][ty];
                float a1r = As[jj][ty + 16];
                float b0r = Bs[jj][tx];
                float b1r = Bs[jj][tx + 16];
                c00 = fmaf(a0r, b0r, c00);
                c01 = fmaf(a0r, b1r, c01);
                c10 = fmaf(a1r, b0r, c10);
                c11 = fmaf(a1r, b1r, c11);
            }
            __syncthreads();
        }

        float* qp = g_Qpart + (size_t)chunk * (NPADQ * KPADX);
        qp[(size_t)(a0 + ty     ) * KPADX + (b0 + tx     )] = c00;
        qp[(size_t)(a0 + ty     ) * KPADX + (b0 + tx + 16)] = c01;
        qp[(size_t)(a0 + ty + 16) * KPADX + (b0 + tx     )] = c10;
        qp[(size_t)(a0 + ty + 16) * KPADX + (b0 + tx + 16)] = c11;
    } else {
        // ---------------- X -> fp16 ----------------
        const int bs = blockIdx.x - NQB;
        const int r  = bs * 4 + (tid >> 6);
        const int c8 = tid & 63;
        if (c8 >= C8MAX || r >= NROWS_PAD) return;
        uint4 hv = make_uint4(0u, 0u, 0u, 0u);
        if (r < N && c8 < (D_DIM / 8)) {
            const float4* p = reinterpret_cast<const float4*>(
                X + (size_t)r * D_DIM + c8 * 8);
            float4 v0 = p[0], v1 = p[1];
            float f[8] = { v0.x, v0.y, v0.z, v0.w, v1.x, v1.y, v1.z, v1.w };
            __half h[8];
            #pragma unroll
            for (int q = 0; q < 8; ++q) h[q] = __float2half_rn(f[q]);
            hv = make_uint4(pack_h2(h[0], h[1]), pack_h2(h[2], h[3]),
                            pack_h2(h[4], h[5]), pack_h2(h[6], h[7]));
        }
        *reinterpret_cast<uint4*>(g_Xh + (size_t)r * KPADX + c8 * 8) = hv;
    }
}

// ---------------------------------------------------------------------------
// convert_q: sum the 8 fp32 partials -> fp16 Q. Block 0 also zeroes the
// output vector (harness poisons it with 0xAA).
// ---------------------------------------------------------------------------
__global__ __launch_bounds__(KPADX)
void convert_q_kernel(float* __restrict__ out, int nout) {
    const int a = blockIdx.x;     // 0..447
    const int b = threadIdx.x;    // 0..415
    float s = 0.f;
    #pragma unroll
    for (int c = 0; c < KSPLIT; ++c)
        s += g_Qpart[(size_t)c * (NPADQ * KPADX) + (size_t)a * KPADX + b];
    g_Qh[(size_t)a * KPADX + b] = __float2half_rn(s);
    if (blockIdx.x == 0)
        for (int i = b; i < nout; i += KPADX) out[i] = 0.f;
}

// ---------------------------------------------------------------------------
// Main kernel: 256 threads (8 warps: 4 M-slices x 2 N-slices).
// Flat loop over 91 (nc, sl) pairs; 5-stage cp.async ring, prefetch
// distance 4, one __syncthreads per slice, no drains.
// Single fp16 product: per kk, 4 LDSM feed 8 HMMA.
// ---------------------------------------------------------------------------
__global__ __launch_bounds__(256, 2)
void gap_mma_kernel(const float* __restrict__ X,
                    const int*  __restrict__ rowseg,
                    float* __restrict__ out,
                    int N) {
    extern __shared__ __align__(16) char smem[];
    float* const sv = reinterpret_cast<float*>(smem + SV_OFF);
    float* const sn = reinterpret_cast<float*>(smem + SN_OFF);

    const int tid  = threadIdx.x;
    const int lane = tid & 31;
    const int wid  = tid >> 5;
    const int wm   = wid & 3;            // M slice 0..3 (32 rows)
    const int wn   = wid >> 2;           // N slice 0..1 (32 cols)
    const int g    = lane >> 2;
    const int tg   = lane & 3;

    const uint32_t s_u32 = smem_u32(smem);

    const int arow_l = lane & 15;
    const int acol_l = (lane >> 4) * 8;
    const int brow_l = (lane & 7) + ((lane >> 4) << 3);
    const int bcol_l = ((lane >> 3) & 1) * 8;

    const size_t row0 = (size_t)blockIdx.x * BM;

    if (tid < BM) { sv[tid] = 0.f; sn[tid] = 0.f; }

    float vp[4] = { 0.f, 0.f, 0.f, 0.f };
    float np[4] = { 0.f, 0.f, 0.f, 0.f };

    const int ra = tid >> 2;
    const int ca = tid & 3;

    // stage slice (sl of chunk nc) into ring buffer buf (3 cp16 per thread)
    auto stage = [&](int sl, int nc, int buf) {
        const int ks = sl * 32;
        const uint32_t sb = s_u32 + (uint32_t)buf * (STAGE_EL * 2);
        const __half* Bh = g_Qh + (size_t)(nc * BN) * KPADX;
        cp16(sb + (O_AHI + ra * AS_ST + ca * 8) * 2,
             g_Xh + (row0 + ra) * KPADX + ks + ca * 8);
        cp16(sb + (O_AHI + (ra + 64) * AS_ST + ca * 8) * 2,
             g_Xh + (row0 + ra + 64) * KPADX + ks + ca * 8);
        cp16(sb + (O_BHI + ra * AS_ST + ca * 8) * 2,
             Bh + (size_t)ra * KPADX + ks + ca * 8);
        cp_commit();
    };

    float c[2][4][4];
    #pragma unroll
    for (int mt = 0; mt < 2; ++mt)
        #pragma unroll
        for (int nt = 0; nt < 4; ++nt)
            #pragma unroll
            for (int q = 0; q < 4; ++q) c[mt][nt][q] = 0.f;

    // prologue: stage gs=0..3 into bufs 0..3
    stage(0, 0, 0);
    stage(1, 0, 1);
    stage(2, 0, 2);
    stage(3, 0, 3);
    cp_wait<3>();
    __syncthreads();

    int sl_c = 0, nc_c = 0, buf_c = 0;   // compute cursor (gs)
    int sl_p = 4, nc_p = 0, buf_p = 4;   // prefetch cursor (gs+4)

    #pragma unroll 1
    for (int gs = 0; gs < TOTS; ++gs) {
        const bool do_stage = (gs + 4 < TOTS);
        if (do_stage) stage(sl_p, nc_p, buf_p);

        // ---- compute on buf_c ----
        const uint32_t sb = s_u32 + (uint32_t)buf_c * (STAGE_EL * 2);
        #pragma unroll
        for (int kk = 0; kk < 2; ++kk) {
            uint32_t a[2][4], b[2][4];
            #pragma unroll
            for (int mt = 0; mt < 2; ++mt) {
                uint32_t ao = (uint32_t)(((wm * 32 + 16 * mt + arow_l) * AS_ST
                                          + kk * 16 + acol_l) * 2);
                ldsm_x4(a[mt], sb + O_AHI * 2 + ao);
            }
            #pragma unroll
            for (int nh = 0; nh < 2; ++nh) {
                uint32_t bo = (uint32_t)(((wn * 32 + 16 * nh + brow_l) * AS_ST
                                          + kk * 16 + bcol_l) * 2);
                ldsm_x4(b[nh], sb + O_BHI * 2 + bo);
            }
            #pragma unroll
            for (int mt = 0; mt < 2; ++mt)
                #pragma unroll
                for (int nt = 0; nt < 4; ++nt)
                    mma_f16(c[mt][nt], a[mt],
                            b[nt >> 1][(nt & 1) * 2],
                            b[nt >> 1][(nt & 1) * 2 + 1]);
        }

        // ---- end of chunk: fold with u = 2x - fp16(x), reset accum ----
        if (sl_c == NSLICE - 1) {
            #pragma unroll
            for (int mt = 0; mt < 2; ++mt) {
                const int    r0l = wm * 32 + 16 * mt + g;
                const size_t R0  = row0 + (size_t)r0l;
                #pragma unroll
                for (int nt = 0; nt < 4; ++nt) {
                    int C0 = nc_c * 64 + wn * 32 + 8 * nt + 2 * tg;
                    if (C0 < D_DIM) {
                        if (R0 < (size_t)N) {
                            float2 x0 = __ldg(reinterpret_cast<const float2*>(
                                X + R0 * D_DIM + C0));
                            float u0x = 2.f * x0.x -
                                __half2float(__float2half_rn(x0.x));
                            float u0y = 2.f * x0.y -
                                __half2float(__float2half_rn(x0.y));
                            vp[2 * mt] = fmaf(u0x, c[mt][nt][0],
                                          fmaf(u0y, c[mt][nt][1], vp[2 * mt]));
                            np[2 * mt] = fmaf(x0.x, x0.x,
                                          fmaf(x0.y, x0.y, np[2 * mt]));
                        }
                        if (R0 + 8 < (size_t)N) {
                            float2 x1 = __ldg(reinterpret_cast<const float2*>(
                                X + (R0 + 8) * D_DIM + C0));
                            float u1x = 2.f * x1.x -
                                __half2float(__float2half_rn(x1.x));
                            float u1y = 2.f * x1.y -
                                __half2float(__float2half_rn(x1.y));
                            vp[2 * mt + 1] = fmaf(u1x, c[mt][nt][2],
                                              fmaf(u1y, c[mt][nt][3], vp[2 * mt + 1]));
                            np[2 * mt + 1] = fmaf(x1.x, x1.x,
                                              fmaf(x1.y, x1.y, np[2 * mt + 1]));
                        }
                    }
                    #pragma unroll
                    for (int q = 0; q < 4; ++q) c[mt][nt][q] = 0.f;
                }
            }
        }

        // ---- wait so buffer gs+1 is complete, then publish ----
        if (gs + 4 < TOTS)      cp_wait<3>();
        else if (gs + 3 < TOTS) cp_wait<2>();
        else if (gs + 2 < TOTS) cp_wait<1>();
        else                    cp_wait<0>();
        __syncthreads();

        ++buf_c; if (buf_c == NSTG) buf_c = 0;
        ++buf_p; if (buf_p == NSTG) buf_p = 0;
        ++sl_c;  if (sl_c == NSLICE) { sl_c = 0; ++nc_c; }
        ++sl_p;  if (sl_p == NSLICE) { sl_p = 0; ++nc_p; }
    }

    // reduce across the 4 lanes sharing each row, then smem accumulate
    #pragma unroll
    for (int i = 0; i < 4; ++i) {
        vp[i] += __shfl_xor_sync(0xFFFFFFFFu, vp[i], 1);
        vp[i] += __shfl_xor_sync(0xFFFFFFFFu, vp[i], 2);
        np[i] += __shfl_xor_sync(0xFFFFFFFFu, np[i], 1);
        np[i] += __shfl_xor_sync(0xFFFFFFFFu, np[i], 2);
    }
    if (tg == 0) {
        #pragma unroll
        for (int i = 0; i < 4; ++i) {
            int mt = i >> 1, hi = i & 1;
            int r  = wm * 32 + 16 * mt + 8 * hi + g;
            atomicAdd(&sv[r], vp[i]);
            atomicAdd(&sn[r], np[i]);
        }
    }
    __syncthreads();

    if (tid < BM) {
        size_t row = row0 + (size_t)tid;
        if (row < (size_t)N) {
            float nr = sn[tid];
            if (nr > 0.f)
                atomicAdd(out + __ldg(rowseg + row), sv[tid] / nr);
        }
    }
}

// ---------------------------------------------------------------------------
extern "C" void kernel_launch(void* const* d_in, const int* in_sizes, int n_in,
                              void* d_out, int out_size) {
    const float* X      = (const float*)d_in[0];
    const float* SP     = (const float*)d_in[1];
    const float* W      = (const float*)d_in[2];
    const int*   rowseg = (const int*)  d_in[4];
    const int*   colseg = (const int*)  d_in[5];
    float* out = (float*)d_out;

    const int N = in_sizes[4];   // environments
    const int M = in_sizes[5];   // support points

    // 1) fused prepass: build-Q partials + X->fp16, concurrent
    prep_kernel<<<NQB + NSB, 256>>>(X, SP, W, colseg, N, M);

    // 2) reduce Q partials -> fp16; also zero the output vector
    convert_q_kernel<<<NPADQ, KPADX>>>(out, out_size);

    // 3) main fused GEMM + quadratic form + segment reduction
    cudaFuncSetAttribute(gap_mma_kernel,
                         cudaFuncAttributeMaxDynamicSharedMemorySize, SMEM_TOTAL);
    int ntiles = (N + BM - 1) / BM;
    gap_mma_kernel<<<ntiles, 256, SMEM_TOTAL>>>(X, rowseg, out, N);
}